// round 13
// baseline (speedup 1.0000x reference)
#include <cuda_runtime.h>

#define Bn 8
#define Hn 512
#define Wn 512
#define HW (Hn*Wn)
#define NPIX (Bn*HW)
#define WPR 16                 // 32-px words per row
#define PW (NPIX/32)           // words per bit-plane = 65536
#define TR 8
#define HALO 7
#define RT (TR+2*HALO)         // 22 tile rows
#define ITEMS (RT*WPR)         // 352
#define NTH 256
#define NCHUNK (Hn/TR)         // 64
#define NBLK (Bn*NCHUNK)       // 512

// Bit-planes: 0-3 elem bits, 4-6 density bits, 7 grav, 8 fall
__device__ unsigned int g_bp[9 * PW];

__device__ __forceinline__ unsigned eq_elem4(
    unsigned p0, unsigned p1, unsigned p2, unsigned p3, int E)
{
    unsigned b0 = (E & 1) ? p0 : ~p0;
    unsigned b1 = (E & 2) ? p1 : ~p1;
    unsigned b2 = (E & 4) ? p2 : ~p2;
    unsigned b3 = (E & 8) ? p3 : ~p3;
    return b0 & b1 & b2 & b3;
}

// ---------------------------------------------------------------------------
// Compress: warp = 128 consecutive pixels (R8 structure). Membership bit via
// bit 29 of the one-hot float (exactly 0.0/1.0); plane bits via shallow
// OR-trees (no dependent select chain); ballots build the plane words.
// Stone-gravity via word-shift of the above-row ch9 ballot with carries.
// ---------------------------------------------------------------------------
__global__ void __launch_bounds__(256) k_compress(
    const float* __restrict__ world, const float* __restrict__ rnd,
    unsigned int* __restrict__ bp)
{
    int gt   = blockIdx.x * 256 + threadIdx.x;
    int gw   = gt >> 5;                       // warp id, 16384 total
    int lane = gt & 31;
    int pxb  = gw << 7;                       // 128 px per warp
    int b    = pxb >> 18;
    int off  = pxb & (HW - 1);
    int h    = off >> 9;
    int ws   = off & 511;                     // 0,128,256,384
    const float* row  = world + (size_t)b * 20 * HW + (size_t)h * Wn;
    const float* rrow = rnd   + (size_t)b * HW      + (size_t)h * Wn;
    const float* p9r  = world + (size_t)b * 20 * HW + (size_t)9 * HW
                      + (size_t)(h - 1) * Wn;   // only deref when h>0

    // above-row stone masks for all 4 words + edge carries
    unsigned m9a[4];
#pragma unroll
    for (int k = 0; k < 4; k++) {
        float a = (h > 0) ? p9r[ws + 32 * k + lane] : 0.f;
        m9a[k] = __ballot_sync(~0u, a > 0.5f);
    }
    unsigned cL = 0, cR = 0;
    if (h > 0 && ws > 0)        cL = (p9r[ws - 1]   > 0.5f) ? 1u : 0u;
    if (h > 0 && ws + 128 < Wn) cR = (p9r[ws + 128] > 0.5f) ? 1u : 0u;

#pragma unroll
    for (int k = 0; k < 4; k++) {
        int w = ws + 32 * k + lane;
        // independent loads + parallel bit extraction (no select chain)
        unsigned t[14];
#pragma unroll
        for (int c = 1; c < 14; c++)
            t[c] = (__float_as_uint(row[(size_t)c * HW + w]) >> 29) & 1u;
        float r = rrow[w];

        unsigned any = t[1]|t[2]|t[3]|t[4]|t[5]|t[6]|t[7]
                     | t[8]|t[9]|t[10]|t[11]|t[12]|t[13];
        unsigned nz  = any ^ 1u;                               // elem == 0
        unsigned e0b = t[1]|t[3]|t[5]|t[7]|t[9]|t[11]|t[13];
        unsigned e1b = t[2]|t[3]|t[6]|t[7]|t[10]|t[11];
        unsigned e2b = t[4]|t[5]|t[6]|t[7]|t[12]|t[13];
        unsigned e3b = t[8]|t[9]|t[10]|t[11]|t[12]|t[13];
        unsigned d0b = nz|t[2]|t[9]|t[10]|t[12];               // den bit0
        unsigned d1b = t[2]|t[3]|t[9]|t[10]|t[11]|t[12];       // den bit1
        unsigned d2b = t[1]|t[5]|t[6]|t[8]|t[13];              // den bit2
        unsigned gnb = nz|t[2]|t[3]|t[4]|t[7]|t[10]|t[11]|t[12]; // grav (non-stone)

        unsigned me0   = __ballot_sync(~0u, e0b);
        unsigned me1   = __ballot_sync(~0u, e1b);
        unsigned me2   = __ballot_sync(~0u, e2b);
        unsigned me3   = __ballot_sync(~0u, e3b);
        unsigned md0   = __ballot_sync(~0u, d0b);
        unsigned md1   = __ballot_sync(~0u, d1b);
        unsigned md2   = __ballot_sync(~0u, d2b);
        unsigned mgns  = __ballot_sync(~0u, gnb);
        unsigned stone = __ballot_sync(~0u, t[9]);
        unsigned mfa   = __ballot_sync(~0u, r > 0.5f);

        unsigned lc = k ? (m9a[k - 1] >> 31) : cL;
        unsigned rc = (k < 3) ? (m9a[k + 1] & 1u) : cR;
        unsigned L = (m9a[k] << 1) | lc;
        unsigned R = (m9a[k] >> 1) | (rc << 31);
        unsigned gv = mgns | (stone & ~(L & R));

        unsigned v = me0;
        v = lane == 1 ? me1 : v;  v = lane == 2 ? me2 : v;
        v = lane == 3 ? me3 : v;  v = lane == 4 ? md0 : v;
        v = lane == 5 ? md1 : v;  v = lane == 6 ? md2 : v;
        v = lane == 7 ? gv  : v;  v = lane == 8 ? mfa : v;
        if (lane < 9) bp[lane * PW + gw * 4 + k] = v;
    }
}

// ---------------------------------------------------------------------------
// Bitwise pass helpers (32 pixels per op)
// ---------------------------------------------------------------------------
__device__ __forceinline__ unsigned eq_den(const unsigned* p, int D) {
    unsigned b0 = (D & 1) ? p[4] : ~p[4];
    unsigned b1 = (D & 2) ? p[5] : ~p[5];
    unsigned b2 = (D & 4) ? p[6] : ~p[6];
    return b0 & b1 & b2;
}
__device__ __forceinline__ unsigned lt_den(const unsigned* p, int D) {
    if (D == 1) return ~p[6] & ~p[5] & ~p[4];
    if (D == 2) return ~p[6] & ~p[5];
    return ~p[6] & ~(p[5] & p[4]);              // D == 3
}
__device__ __forceinline__ unsigned gt3(
    unsigned x2, unsigned x1, unsigned x0,
    unsigned y2, unsigned y1, unsigned y0)
{
    unsigned eq2 = ~(x2 ^ y2), eq1 = ~(x1 ^ y1);
    return (x2 & ~y2) | (eq2 & x1 & ~y1) | (eq2 & eq1 & x0 & ~y0);
}

__shared__ unsigned s_mov[2][8][ITEMS];
__shared__ unsigned s_fall[ITEMS];
__shared__ unsigned s_dg[ITEMS];

template <int D>
__device__ __forceinline__ void grav_pass(
    unsigned (*src)[ITEMS], unsigned (*dst)[ITEMS], int i, int c)
{
    int rw = i * WPR + c;
    int ra = rw - WPR, rb = rw + WPR;
    unsigned s[8], a[8], bb[8];
#pragma unroll
    for (int p = 0; p < 8; p++) { s[p] = src[p][rw]; a[p] = src[p][ra]; bb[p] = src[p][rb]; }
    unsigned bel = eq_den(s, D) & lt_den(bb, D) & s[7] & bb[7];
    unsigned abv = eq_den(a, D) & lt_den(s, D) & a[7] & s[7];
    unsigned keep = ~(bel | abv);
#pragma unroll
    for (int p = 0; p < 8; p++)
        dst[p][rw] = (bel & bb[p]) | (abv & a[p]) | (keep & s[p]);
    s_dg[rw] |= abv;
}

template <int E, int LEFT>
__device__ __forceinline__ void diag_pass(
    unsigned (*src)[ITEMS], unsigned (*dst)[ITEMS], int i, int c)
{
    int rw = i * WPR + c;
    int wm = (c - 1) & 15, wp = (c + 1) & 15;
    int ba = (i - 1) * WPR, bbr = (i + 1) * WPR;

    unsigned s[8], bl[8], ar[8];
#pragma unroll
    for (int p = 0; p < 8; p++) s[p] = src[p][rw];
    unsigned sd = s_dg[rw], sf = s_fall[rw];
    unsigned bl_dg, ar_dg, ar_f;
    if (LEFT) {
#pragma unroll
        for (int p = 0; p < 8; p++) {
            bl[p] = __funnelshift_l(src[p][bbr + wm], src[p][bbr + c], 1);
            ar[p] = __funnelshift_r(src[p][ba + c], src[p][ba + wp], 1);
        }
        bl_dg = __funnelshift_l(s_dg[bbr + wm], s_dg[bbr + c], 1);
        ar_dg = __funnelshift_r(s_dg[ba + c], s_dg[ba + wp], 1);
        ar_f  = __funnelshift_r(s_fall[ba + c], s_fall[ba + wp], 1);
    } else {
#pragma unroll
        for (int p = 0; p < 8; p++) {
            bl[p] = __funnelshift_r(src[p][bbr + c], src[p][bbr + wp], 1);
            ar[p] = __funnelshift_l(src[p][ba + wm], src[p][ba + c], 1);
        }
        bl_dg = __funnelshift_r(s_dg[bbr + c], s_dg[bbr + wp], 1);
        ar_dg = __funnelshift_l(s_dg[ba + wm], s_dg[ba + c], 1);
        ar_f  = __funnelshift_l(s_fall[ba + wm], s_fall[ba + c], 1);
    }
    unsigned ms  = LEFT ? sf : ~sf;
    unsigned mar = LEFT ? ar_f : ~ar_f;
    unsigned bbl = eq_elem4(s[0], s[1], s[2], s[3], E) & ~bl_dg & ~sd & ms
                 & gt3(s[6], s[5], s[4], bl[6], bl[5], bl[4]) & s[7] & bl[7];
    unsigned bar = eq_elem4(ar[0], ar[1], ar[2], ar[3], E) & ~ar_dg & ~sd & mar
                 & gt3(ar[6], ar[5], ar[4], s[6], s[5], s[4]) & ar[7] & s[7];
    unsigned keep = ~(bbl | bar);
#pragma unroll
    for (int p = 0; p < 8; p++)
        dst[p][rw] = (bbl & bl[p]) | (bar & ar[p]) | (keep & s[p]);
}

// ---------------------------------------------------------------------------
// Fused sim (bit-sliced, shrinking ranges) + decompress.
// TR=8, 256 threads, 512 blocks -> whole grid resident in one wave.
// ---------------------------------------------------------------------------
__global__ void __launch_bounds__(NTH, 4) k_sim(
    const unsigned int* __restrict__ bp, float* __restrict__ out)
{
    int tid = threadIdx.x;
    int b = blockIdx.x >> 6, chunk = blockIdx.x & 63;
    int r0 = chunk * TR;

    // Load 9 planes (with vertical wrap) into SMEM
#pragma unroll
    for (int p = 0; p < 9; p++) {
        const unsigned* pp = bp + (size_t)p * PW + (size_t)b * (Hn * WPR);
        for (int rw = tid; rw < ITEMS; rw += NTH) {
            int i = rw >> 4, wq = rw & 15;
            int gr = (r0 - HALO + i) & (Hn - 1);
            unsigned v = pp[gr * WPR + wq];
            if (p < 8) s_mov[0][p][rw] = v; else s_fall[rw] = v;
        }
    }
    for (int rw = tid; rw < ITEMS; rw += NTH) s_dg[rw] = 0;
    __syncthreads();

    // Pass k computes exactly rows [k, RT-k)
    for (int t2 = tid; t2 < (RT - 2) * WPR; t2 += NTH)
        grav_pass<1>(s_mov[0], s_mov[1], (t2 >> 4) + 1, t2 & 15);
    __syncthreads();
    for (int t2 = tid; t2 < (RT - 4) * WPR; t2 += NTH)
        grav_pass<2>(s_mov[1], s_mov[0], (t2 >> 4) + 2, t2 & 15);
    __syncthreads();
    for (int t2 = tid; t2 < (RT - 6) * WPR; t2 += NTH)
        grav_pass<3>(s_mov[0], s_mov[1], (t2 >> 4) + 3, t2 & 15);
    __syncthreads();
    for (int t2 = tid; t2 < (RT - 8) * WPR; t2 += NTH)
        diag_pass<2, 1>(s_mov[1], s_mov[0], (t2 >> 4) + 4, t2 & 15);
    __syncthreads();
    for (int t2 = tid; t2 < (RT - 10) * WPR; t2 += NTH)
        diag_pass<2, 0>(s_mov[0], s_mov[1], (t2 >> 4) + 5, t2 & 15);
    __syncthreads();
    for (int t2 = tid; t2 < (RT - 12) * WPR; t2 += NTH)
        diag_pass<12, 1>(s_mov[1], s_mov[0], (t2 >> 4) + 6, t2 & 15);
    __syncthreads();
    for (int t2 = tid; t2 < (RT - 14) * WPR; t2 += NTH)
        diag_pass<12, 0>(s_mov[0], s_mov[1], (t2 >> 4) + 7, t2 & 15);
    __syncthreads();
    // final state in s_mov[1], valid rows [HALO, HALO+TR)

    // Decompress valid rows to the 20-channel f32 world
    float* ob = out + (size_t)b * 20 * HW;
    for (int g2 = tid; g2 < TR * 128; g2 += NTH) {
        int ii = (g2 >> 7) + HALO;
        int q  = g2 & 127;                 // float4 group within row
        int wq = q >> 3;
        int k  = (q & 7) * 4;
        int rw = ii * WPR + wq;
        unsigned p0 = s_mov[1][0][rw], p1 = s_mov[1][1][rw];
        unsigned p2 = s_mov[1][2][rw], p3 = s_mov[1][3][rw];
        unsigned p4 = s_mov[1][4][rw], p5 = s_mov[1][5][rw];
        unsigned p6 = s_mov[1][6][rw], p7 = s_mov[1][7][rw];
        int e[4]; float dn[4], gv[4];
#pragma unroll
        for (int j = 0; j < 4; j++) {
            int kk = k + j;
            e[j] = ((p0 >> kk) & 1) | (((p1 >> kk) & 1) << 1)
                 | (((p2 >> kk) & 1) << 2) | (((p3 >> kk) & 1) << 3);
            dn[j] = (float)(((p4 >> kk) & 1) | (((p5 >> kk) & 1) << 1)
                          | (((p6 >> kk) & 1) << 2));
            gv[j] = (float)((p7 >> kk) & 1);
        }
        int gh = r0 + ii - HALO;
        float* op = ob + (size_t)gh * Wn + q * 4;
#pragma unroll
        for (int ch = 0; ch < 14; ch++) {
            float4 v = make_float4(e[0] == ch ? 1.f : 0.f, e[1] == ch ? 1.f : 0.f,
                                   e[2] == ch ? 1.f : 0.f, e[3] == ch ? 1.f : 0.f);
            *reinterpret_cast<float4*>(op + (size_t)ch * HW) = v;
        }
        *reinterpret_cast<float4*>(op + (size_t)14 * HW) =
            make_float4(dn[0], dn[1], dn[2], dn[3]);
        *reinterpret_cast<float4*>(op + (size_t)15 * HW) =
            make_float4(gv[0], gv[1], gv[2], gv[3]);
        float4 z = make_float4(0.f, 0.f, 0.f, 0.f);
#pragma unroll
        for (int ch = 16; ch < 20; ch++)
            *reinterpret_cast<float4*>(op + (size_t)ch * HW) = z;
    }
}

// ---------------------------------------------------------------------------
extern "C" void kernel_launch(void* const* d_in, const int* in_sizes, int n_in,
                              void* d_out, int out_size)
{
    int wi = 0, ri = 1;
    if (n_in >= 2 && in_sizes[0] < in_sizes[1]) { wi = 1; ri = 0; }
    const float* world = (const float*)d_in[wi];
    const float* rnd   = (const float*)d_in[ri];
    float* out = (float*)d_out;

    unsigned int* bp;
    cudaGetSymbolAddress((void**)&bp, g_bp);

    k_compress<<<(NPIX/4) / 256, 256>>>(world, rnd, bp);
    k_sim<<<NBLK, NTH>>>(bp, out);
}

// round 16
// speedup vs baseline: 1.1932x; 1.1932x over previous
#include <cuda_runtime.h>

#define Bn 8
#define Hn 512
#define Wn 512
#define HW (Hn*Wn)
#define NPIX (Bn*HW)
#define WPR 16                 // 32-px words per row
#define PW (NPIX/32)           // words per bit-plane = 65536
#define TR 16
#define HALO 7
#define RT (TR+2*HALO)         // 30 tile rows
#define ITEMS (RT*WPR)         // 480
#define NTH 512
#define NBLK (Bn*(Hn/TR))      // 256

// Bit-planes: 0-3 elem bits, 4-6 density bits, 7 grav, 8 fall
__device__ unsigned int g_bp[9 * PW];

__host__ __device__ constexpr unsigned long long make_den_lut() {
    constexpr int d[16] = {1,4,3,2,0,4,4,0,4,3,3,2,3,4,0,0};
    unsigned long long v = 0;
    for (int i = 0; i < 16; i++) v |= (unsigned long long)d[i] << (3*i);
    return v;
}
constexpr unsigned long long DEN_LUT = make_den_lut();
#define GRV_LUT 0x1E9Du

__device__ __forceinline__ unsigned eq_elem4(
    unsigned p0, unsigned p1, unsigned p2, unsigned p3, int E)
{
    unsigned b0 = (E & 1) ? p0 : ~p0;
    unsigned b1 = (E & 2) ? p1 : ~p1;
    unsigned b2 = (E & 4) ? p2 : ~p2;
    unsigned b3 = (E & 8) ? p3 : ~p3;
    return b0 & b1 & b2 & b3;
}

// ---------------------------------------------------------------------------
// Compress (R8, measured 25.4us): warp = 128 consecutive pixels. Per word k,
// lane loads pixel ws+32k+lane (coalesced), 9 ballots build the plane words.
// Stone-gravity rule via word-shift of the above-row ch9 ballot mask with
// cross-word carries (zero-padded at absolute H/W borders).
// ---------------------------------------------------------------------------
__global__ void __launch_bounds__(256) k_compress(
    const float* __restrict__ world, const float* __restrict__ rnd,
    unsigned int* __restrict__ bp)
{
    int gt   = blockIdx.x * 256 + threadIdx.x;
    int gw   = gt >> 5;                       // warp id, 16384 total
    int lane = gt & 31;
    int pxb  = gw << 7;                       // 128 px per warp
    int b    = pxb >> 18;
    int off  = pxb & (HW - 1);
    int h    = off >> 9;
    int ws   = off & 511;                     // 0,128,256,384
    const float* row  = world + (size_t)b * 20 * HW + (size_t)h * Wn;
    const float* rrow = rnd   + (size_t)b * HW      + (size_t)h * Wn;
    const float* p9r  = world + (size_t)b * 20 * HW + (size_t)9 * HW
                      + (size_t)(h - 1) * Wn;   // only deref when h>0

    // above-row stone masks for all 4 words + edge carries
    unsigned m9a[4];
#pragma unroll
    for (int k = 0; k < 4; k++) {
        float a = (h > 0) ? p9r[ws + 32 * k + lane] : 0.f;
        m9a[k] = __ballot_sync(~0u, a > 0.5f);
    }
    unsigned cL = 0, cR = 0;                  // uniform broadcast loads
    if (h > 0 && ws > 0)        cL = (p9r[ws - 1]   > 0.5f) ? 1u : 0u;
    if (h > 0 && ws + 128 < Wn) cR = (p9r[ws + 128] > 0.5f) ? 1u : 0u;

#pragma unroll
    for (int k = 0; k < 4; k++) {
        int w = ws + 32 * k + lane;
        int e = 0;
#pragma unroll
        for (int c = 1; c < 14; c++)
            if (row[(size_t)c * HW + w] > 0.5f) e = c;
        int den = (int)((DEN_LUT >> (3 * e)) & 7);
        int gvt = (GRV_LUT >> e) & 1;
        float r = rrow[w];

        unsigned me0 = __ballot_sync(~0u, e & 1);
        unsigned me1 = __ballot_sync(~0u, e & 2);
        unsigned me2 = __ballot_sync(~0u, e & 4);
        unsigned me3 = __ballot_sync(~0u, e & 8);
        unsigned md0 = __ballot_sync(~0u, den & 1);
        unsigned md1 = __ballot_sync(~0u, den & 2);
        unsigned md2 = __ballot_sync(~0u, den & 4);
        unsigned mg  = __ballot_sync(~0u, gvt);
        unsigned mfa = __ballot_sync(~0u, r > 0.5f);

        unsigned stone = me0 & ~me1 & ~me2 & me3;     // e == 9
        unsigned lc = k ? (m9a[k - 1] >> 31) : cL;
        unsigned rc = (k < 3) ? (m9a[k + 1] & 1u) : cR;
        unsigned L = (m9a[k] << 1) | lc;
        unsigned R = (m9a[k] >> 1) | (rc << 31);
        unsigned gv = (mg & ~stone) | (stone & ~(L & R));

        unsigned v = me0;
        v = lane == 1 ? me1 : v;  v = lane == 2 ? me2 : v;
        v = lane == 3 ? me3 : v;  v = lane == 4 ? md0 : v;
        v = lane == 5 ? md1 : v;  v = lane == 6 ? md2 : v;
        v = lane == 7 ? gv  : v;  v = lane == 8 ? mfa : v;
        if (lane < 9) bp[lane * PW + gw * 4 + k] = v;
    }
}

// ---------------------------------------------------------------------------
// Bitwise pass helpers (32 pixels per op)
// ---------------------------------------------------------------------------
__device__ __forceinline__ unsigned eq_den(const unsigned* p, int D) {
    unsigned b0 = (D & 1) ? p[4] : ~p[4];
    unsigned b1 = (D & 2) ? p[5] : ~p[5];
    unsigned b2 = (D & 4) ? p[6] : ~p[6];
    return b0 & b1 & b2;
}
__device__ __forceinline__ unsigned lt_den(const unsigned* p, int D) {
    if (D == 1) return ~p[6] & ~p[5] & ~p[4];
    if (D == 2) return ~p[6] & ~p[5];
    return ~p[6] & ~(p[5] & p[4]);              // D == 3
}
__device__ __forceinline__ unsigned gt3(
    unsigned x2, unsigned x1, unsigned x0,
    unsigned y2, unsigned y1, unsigned y0)
{
    unsigned eq2 = ~(x2 ^ y2), eq1 = ~(x1 ^ y1);
    return (x2 & ~y2) | (eq2 & x1 & ~y1) | (eq2 & eq1 & x0 & ~y0);
}

__shared__ unsigned s_mov[2][8][ITEMS];
__shared__ unsigned s_fall[ITEMS];
__shared__ unsigned s_dg[ITEMS];

template <int D>
__device__ __forceinline__ void grav_pass(
    unsigned (*src)[ITEMS], unsigned (*dst)[ITEMS], int i, int c)
{
    int rw = i * WPR + c;
    int ra = rw - WPR, rb = rw + WPR;
    unsigned s[8], a[8], bb[8];
#pragma unroll
    for (int p = 0; p < 8; p++) { s[p] = src[p][rw]; a[p] = src[p][ra]; bb[p] = src[p][rb]; }
    unsigned bel = eq_den(s, D) & lt_den(bb, D) & s[7] & bb[7];
    unsigned abv = eq_den(a, D) & lt_den(s, D) & a[7] & s[7];
    unsigned keep = ~(bel | abv);
#pragma unroll
    for (int p = 0; p < 8; p++)
        dst[p][rw] = (bel & bb[p]) | (abv & a[p]) | (keep & s[p]);
    s_dg[rw] |= abv;
}

template <int E, int LEFT>
__device__ __forceinline__ void diag_pass(
    unsigned (*src)[ITEMS], unsigned (*dst)[ITEMS], int i, int c)
{
    int rw = i * WPR + c;
    int wm = (c - 1) & 15, wp = (c + 1) & 15;
    int ba = (i - 1) * WPR, bbr = (i + 1) * WPR;

    unsigned s[8], bl[8], ar[8];
#pragma unroll
    for (int p = 0; p < 8; p++) s[p] = src[p][rw];
    unsigned sd = s_dg[rw], sf = s_fall[rw];
    unsigned bl_dg, ar_dg, ar_f;
    if (LEFT) {
#pragma unroll
        for (int p = 0; p < 8; p++) {
            bl[p] = __funnelshift_l(src[p][bbr + wm], src[p][bbr + c], 1);
            ar[p] = __funnelshift_r(src[p][ba + c], src[p][ba + wp], 1);
        }
        bl_dg = __funnelshift_l(s_dg[bbr + wm], s_dg[bbr + c], 1);
        ar_dg = __funnelshift_r(s_dg[ba + c], s_dg[ba + wp], 1);
        ar_f  = __funnelshift_r(s_fall[ba + c], s_fall[ba + wp], 1);
    } else {
#pragma unroll
        for (int p = 0; p < 8; p++) {
            bl[p] = __funnelshift_r(src[p][bbr + c], src[p][bbr + wp], 1);
            ar[p] = __funnelshift_l(src[p][ba + wm], src[p][ba + c], 1);
        }
        bl_dg = __funnelshift_r(s_dg[bbr + c], s_dg[bbr + wp], 1);
        ar_dg = __funnelshift_l(s_dg[ba + wm], s_dg[ba + c], 1);
        ar_f  = __funnelshift_l(s_fall[ba + wm], s_fall[ba + c], 1);
    }
    unsigned ms  = LEFT ? sf : ~sf;
    unsigned mar = LEFT ? ar_f : ~ar_f;
    unsigned bbl = eq_elem4(s[0], s[1], s[2], s[3], E) & ~bl_dg & ~sd & ms
                 & gt3(s[6], s[5], s[4], bl[6], bl[5], bl[4]) & s[7] & bl[7];
    unsigned bar = eq_elem4(ar[0], ar[1], ar[2], ar[3], E) & ~ar_dg & ~sd & mar
                 & gt3(ar[6], ar[5], ar[4], s[6], s[5], s[4]) & ar[7] & s[7];
    unsigned keep = ~(bbl | bar);
#pragma unroll
    for (int p = 0; p < 8; p++)
        dst[p][rw] = (bbl & bl[p]) | (bar & ar[p]) | (keep & s[p]);
}

// ---------------------------------------------------------------------------
// Fused sim (R9, measured 31.8us): bit-sliced shrinking-range passes in SMEM
// + decompress to the f32 world. TR=16, 512 threads, 256 blocks.
// ---------------------------------------------------------------------------
__global__ void __launch_bounds__(NTH, 2) k_sim(
    const unsigned int* __restrict__ bp, float* __restrict__ out)
{
    int tid = threadIdx.x;
    int b = blockIdx.x >> 5, chunk = blockIdx.x & 31;
    int r0 = chunk * TR;

    // Load 9 planes (with vertical wrap) into SMEM
#pragma unroll
    for (int p = 0; p < 9; p++) {
        const unsigned* pp = bp + (size_t)p * PW + (size_t)b * (Hn * WPR);
        for (int rw = tid; rw < ITEMS; rw += NTH) {
            int i = rw >> 4, wq = rw & 15;
            int gr = (r0 - HALO + i) & (Hn - 1);
            unsigned v = pp[gr * WPR + wq];
            if (p < 8) s_mov[0][p][rw] = v; else s_fall[rw] = v;
        }
    }
    for (int rw = tid; rw < ITEMS; rw += NTH) s_dg[rw] = 0;
    __syncthreads();

    // Pass k computes exactly rows [k, RT-k)
    int i = (tid >> 4), c = tid & 15;
    if (tid < (RT- 2)*WPR) grav_pass<1>(s_mov[0], s_mov[1], i + 1, c);    __syncthreads();
    if (tid < (RT- 4)*WPR) grav_pass<2>(s_mov[1], s_mov[0], i + 2, c);    __syncthreads();
    if (tid < (RT- 6)*WPR) grav_pass<3>(s_mov[0], s_mov[1], i + 3, c);    __syncthreads();
    if (tid < (RT- 8)*WPR) diag_pass<2 ,1>(s_mov[1], s_mov[0], i + 4, c); __syncthreads();
    if (tid < (RT-10)*WPR) diag_pass<2 ,0>(s_mov[0], s_mov[1], i + 5, c); __syncthreads();
    if (tid < (RT-12)*WPR) diag_pass<12,1>(s_mov[1], s_mov[0], i + 6, c); __syncthreads();
    if (tid < (RT-14)*WPR) diag_pass<12,0>(s_mov[0], s_mov[1], i + 7, c); __syncthreads();
    // final state in s_mov[1], valid rows [HALO, HALO+TR)

    // Decompress valid rows to the 20-channel f32 world
    float* ob = out + (size_t)b * 20 * HW;
    for (int g2 = tid; g2 < TR * 128; g2 += NTH) {
        int ii = (g2 >> 7) + HALO;
        int q  = g2 & 127;                 // float4 group within row
        int wq = q >> 3;
        int k  = (q & 7) * 4;
        int rw = ii * WPR + wq;
        unsigned p0 = s_mov[1][0][rw], p1 = s_mov[1][1][rw];
        unsigned p2 = s_mov[1][2][rw], p3 = s_mov[1][3][rw];
        unsigned p4 = s_mov[1][4][rw], p5 = s_mov[1][5][rw];
        unsigned p6 = s_mov[1][6][rw], p7 = s_mov[1][7][rw];
        int e[4]; float dn[4], gv[4];
#pragma unroll
        for (int j = 0; j < 4; j++) {
            int kk = k + j;
            e[j] = ((p0 >> kk) & 1) | (((p1 >> kk) & 1) << 1)
                 | (((p2 >> kk) & 1) << 2) | (((p3 >> kk) & 1) << 3);
            dn[j] = (float)(((p4 >> kk) & 1) | (((p5 >> kk) & 1) << 1)
                          | (((p6 >> kk) & 1) << 2));
            gv[j] = (float)((p7 >> kk) & 1);
        }
        int gh = r0 + ii - HALO;
        float* op = ob + (size_t)gh * Wn + q * 4;
#pragma unroll
        for (int ch = 0; ch < 14; ch++) {
            float4 v = make_float4(e[0] == ch ? 1.f : 0.f, e[1] == ch ? 1.f : 0.f,
                                   e[2] == ch ? 1.f : 0.f, e[3] == ch ? 1.f : 0.f);
            *reinterpret_cast<float4*>(op + (size_t)ch * HW) = v;
        }
        *reinterpret_cast<float4*>(op + (size_t)14 * HW) =
            make_float4(dn[0], dn[1], dn[2], dn[3]);
        *reinterpret_cast<float4*>(op + (size_t)15 * HW) =
            make_float4(gv[0], gv[1], gv[2], gv[3]);
        float4 z = make_float4(0.f, 0.f, 0.f, 0.f);
#pragma unroll
        for (int ch = 16; ch < 20; ch++)
            *reinterpret_cast<float4*>(op + (size_t)ch * HW) = z;
    }
}

// ---------------------------------------------------------------------------
extern "C" void kernel_launch(void* const* d_in, const int* in_sizes, int n_in,
                              void* d_out, int out_size)
{
    int wi = 0, ri = 1;
    if (n_in >= 2 && in_sizes[0] < in_sizes[1]) { wi = 1; ri = 0; }
    const float* world = (const float*)d_in[wi];
    const float* rnd   = (const float*)d_in[ri];
    float* out = (float*)d_out;

    unsigned int* bp;
    cudaGetSymbolAddress((void**)&bp, g_bp);

    k_compress<<<(NPIX/4) / 256, 256>>>(world, rnd, bp);
    k_sim<<<NBLK, NTH>>>(bp, out);
}